// round 1
// baseline (speedup 1.0000x reference)
#include <cuda_runtime.h>
#include <math.h>

#define D 56
#define H 501
#define T 277
#define O 76
#define B 256
#define H3 1503
#define NBLK 128
#define NTHR 256
#define KC 32
#define BM 64
#define BN 16   /* per gate */

// ---------------- static device scratch (no allocations allowed) ----------------
__device__ float d_hin[B * D];
__device__ float d_g0[B * H3];
__device__ float d_ysA[T * B * H];     // 142 MB
__device__ float d_ysB[T * B * H];     // 142 MB
__device__ float d_gbuf[T * B * H3];   // 426 MB (reused for g1 then g2)

// ---------------- grid barrier ----------------
__device__ unsigned int g_arrive = 0;
__device__ volatile unsigned int g_gen = 0;

__device__ __forceinline__ void grid_sync() {
    __syncthreads();
    if (threadIdx.x == 0) {
        __threadfence();
        unsigned int gen = g_gen;
        if (atomicAdd(&g_arrive, 1u) == (unsigned)(NBLK - 1)) {
            g_arrive = 0;
            __threadfence();
            g_gen = gen + 1;
        } else {
            while (g_gen == gen) { }
        }
        __threadfence();
    }
    __syncthreads();
}

// ---------------- packed f32x2 helpers ----------------
__device__ __forceinline__ unsigned long long dup_f32(float x) {
    unsigned long long r;
    unsigned int u = __float_as_uint(x);
    asm("mov.b64 %0, {%1, %1};" : "=l"(r) : "r"(u));
    return r;
}
__device__ __forceinline__ unsigned long long ffma2(unsigned long long a,
                                                    unsigned long long b,
                                                    unsigned long long c) {
    unsigned long long d;
    asm("fma.rn.f32x2 %0, %1, %2, %3;" : "=l"(d) : "l"(a), "l"(b), "l"(c));
    return d;
}
__device__ __forceinline__ float2 unpack2(unsigned long long v) {
    unsigned int lo, hi;
    asm("mov.b64 {%0, %1}, %2;" : "=r"(lo), "=r"(hi) : "l"(v));
    return make_float2(__uint_as_float(lo), __uint_as_float(hi));
}

// ---------------- shared memory ----------------
struct SMemG {
    float hs[KC][BM + 2];        // k-major h tile (pad 2 keeps 8B align + fewer conflicts)
    float ws[3][KC][BN + 1];     // 3-gate W tile
};
union SMem {
    SMemG g;
    float rows[8][H + 1];        // fc2 staging
};

// ---------------- fused 3-gate tile GEMM: acc[g] = hsrc(m0:m0+64,:) . W[g*H+n0+j,:] ----------------
__device__ __forceinline__ void tile3(SMem& sm, const float* __restrict__ hsrc,
                                      const float* __restrict__ W,
                                      int m0, int n0, unsigned long long acc[3][2]) {
    const int tid = threadIdx.x;
    const int tx = tid & 15;
    const int mrow = (tid >> 4) * 4;
    acc[0][0] = acc[0][1] = acc[1][0] = acc[1][1] = acc[2][0] = acc[2][1] = 0ull;
    if (hsrc == nullptr) return;  // h == 0 -> hg == 0 (uniform across block)

    const int lm = tid >> 5;   // 0..7
    const int lk = tid & 31;

    for (int k0 = 0; k0 < H; k0 += KC) {
        // stage h tile (k-major)
#pragma unroll
        for (int i = 0; i < 8; i++) {
            int mm = lm + i * 8;
            int k = k0 + lk;
            float v = (k < H) ? hsrc[(m0 + mm) * H + k] : 0.f;
            sm.g.hs[lk][mm] = v;
        }
        // stage 3-gate W tile
#pragma unroll
        for (int i = 0; i < 6; i++) {
            int e = tid + i * NTHR;
            int g = e >> 9;
            int rem = e & 511;
            int j = rem >> 5;
            int kk = rem & 31;
            int n = n0 + j;
            int k = k0 + kk;
            float v = (n < H && k < H) ? W[(g * H + n) * H + k] : 0.f;
            sm.g.ws[g][kk][j] = v;
        }
        __syncthreads();
#pragma unroll
        for (int kk = 0; kk < KC; kk++) {
            unsigned long long hp0 = *(const unsigned long long*)&sm.g.hs[kk][mrow];
            unsigned long long hp1 = *(const unsigned long long*)&sm.g.hs[kk][mrow + 2];
            unsigned long long w0 = dup_f32(sm.g.ws[0][kk][tx]);
            unsigned long long w1 = dup_f32(sm.g.ws[1][kk][tx]);
            unsigned long long w2 = dup_f32(sm.g.ws[2][kk][tx]);
            acc[0][0] = ffma2(hp0, w0, acc[0][0]);
            acc[0][1] = ffma2(hp1, w0, acc[0][1]);
            acc[1][0] = ffma2(hp0, w1, acc[1][0]);
            acc[1][1] = ffma2(hp1, w1, acc[1][1]);
            acc[2][0] = ffma2(hp0, w2, acc[2][0]);
            acc[2][1] = ffma2(hp1, w2, acc[2][1]);
        }
        __syncthreads();
    }
}

// ---------------- one GRU timestep (all 128 blocks, one tile each) ----------------
__device__ void scan_step(SMem& sm, const float* __restrict__ hprev,
                          const float* __restrict__ g,
                          const float* __restrict__ Whh,
                          const float* __restrict__ bhh,
                          float* __restrict__ hout) {
    const int tile = blockIdx.x;   // 0..127 = 4 M-tiles x 32 N-tiles
    const int mt = tile >> 5;
    const int nt = tile & 31;
    const int m0 = mt * BM;
    const int n0 = nt * BN;

    unsigned long long acc[3][2];
    tile3(sm, hprev, Whh, m0, n0, acc);

    const int tx = threadIdx.x & 15;
    const int ty = threadIdx.x >> 4;
    const int n = n0 + tx;
    if (n < H) {
        const float br = bhh[n];
        const float bz = bhh[H + n];
        const float bn = bhh[2 * H + n];
        float2 r0 = unpack2(acc[0][0]), r1 = unpack2(acc[0][1]);
        float2 z0 = unpack2(acc[1][0]), z1 = unpack2(acc[1][1]);
        float2 n0v = unpack2(acc[2][0]), n1v = unpack2(acc[2][1]);
        float ar[4] = {r0.x, r0.y, r1.x, r1.y};
        float az[4] = {z0.x, z0.y, z1.x, z1.y};
        float an[4] = {n0v.x, n0v.y, n1v.x, n1v.y};
#pragma unroll
        for (int i = 0; i < 4; i++) {
            const int m = m0 + ty * 4 + i;
            const float hp = hprev ? hprev[m * H + n] : 0.f;
            const float* gr = g + m * H3;
            float r = 1.f / (1.f + __expf(-(gr[n] + ar[i] + br)));
            float z = 1.f / (1.f + __expf(-(gr[H + n] + az[i] + bz)));
            float nn = tanhf(gr[2 * H + n] + r * (an[i] + bn));
            hout[m * H + n] = (1.f - z) * nn + z * hp;
        }
    }
}

// ---------------- batched input-gate GEMM: G(M x 3H) = Y(M x H) . Wih^T + bih ----------------
__device__ void gate_gemm(SMem& sm, const float* __restrict__ Y,
                          const float* __restrict__ Wih,
                          const float* __restrict__ bih,
                          float* __restrict__ G, int M) {
    const int Mtiles = M / BM;
    const int total = Mtiles * 32;
    for (int tile = blockIdx.x; tile < total; tile += NBLK) {
        const int mt = tile >> 5;
        const int nt = tile & 31;
        const int m0 = mt * BM;
        const int n0 = nt * BN;

        unsigned long long acc[3][2];
        tile3(sm, Y, Wih, m0, n0, acc);

        const int tx = threadIdx.x & 15;
        const int ty = threadIdx.x >> 4;
        const int n = n0 + tx;
        if (n < H) {
#pragma unroll
            for (int g = 0; g < 3; g++) {
                float2 p0 = unpack2(acc[g][0]);
                float2 p1 = unpack2(acc[g][1]);
                float a[4] = {p0.x, p0.y, p1.x, p1.y};
                const float bb = bih[g * H + n];
#pragma unroll
                for (int i = 0; i < 4; i++) {
                    const int m = m0 + ty * 4 + i;
                    G[m * H3 + g * H + n] = a[i] + bb;
                }
            }
        }
    }
}

// ---------------- fc2 + permute to (B, O, T) ----------------
__device__ void fc2_phase(SMem& sm, const float* __restrict__ Y,
                          const float* __restrict__ W,
                          const float* __restrict__ bias,
                          float* __restrict__ out) {
    const int wid = threadIdx.x >> 5;
    const int lane = threadIdx.x & 31;
    const int M = T * B;
    for (int base = blockIdx.x * 8; base < M; base += NBLK * 8) {
        const int row = base + wid;
        if (row < M) {
            for (int k = lane; k < H; k += 32) sm.rows[wid][k] = Y[row * H + k];
            __syncwarp();
            const int t = row / B;
            const int b = row % B;
            for (int o = lane; o < O; o += 32) {
                float acc = bias[o];
                const float* w = W + o * H;
                for (int k = 0; k < H; k++) acc += sm.rows[wid][k] * w[k];
                out[(b * O + o) * T + t] = acc;
            }
            __syncwarp();
        }
    }
}

// ---------------- persistent mega-kernel ----------------
__global__ void __launch_bounds__(NTHR) decoder_kernel(
    const float* __restrict__ x,
    const float* __restrict__ fc1_w, const float* __restrict__ fc1_b,
    const float* __restrict__ w_ih0, const float* __restrict__ w_hh0,
    const float* __restrict__ b_ih0, const float* __restrict__ b_hh0,
    const float* __restrict__ w_ih1, const float* __restrict__ w_hh1,
    const float* __restrict__ b_ih1, const float* __restrict__ b_hh1,
    const float* __restrict__ w_ih2, const float* __restrict__ w_hh2,
    const float* __restrict__ b_ih2, const float* __restrict__ b_hh2,
    const float* __restrict__ fc2_w, const float* __restrict__ fc2_b,
    float* __restrict__ out) {
    __shared__ SMem sm;
    const int gt = blockIdx.x * NTHR + threadIdx.x;
    const int GT = NBLK * NTHR;

    // fc1 + relu
    for (int i = gt; i < B * D; i += GT) {
        const int b = i / D, d = i % D;
        float acc = fc1_b[d];
        for (int k = 0; k < D; k++) acc += x[b * D + k] * fc1_w[d * D + k];
        d_hin[i] = fmaxf(acc, 0.f);
    }
    grid_sync();

    // g0 = h_in @ w_ih0^T + b_ih0 (constant over t)
    for (int i = gt; i < B * H3; i += GT) {
        const int b = i / H3, j = i % H3;
        float acc = b_ih0[j];
        for (int k = 0; k < D; k++) acc += d_hin[b * D + k] * w_ih0[j * D + k];
        d_g0[i] = acc;
    }
    grid_sync();

    // layer 0 scan -> ysA
    for (int t = 0; t < T; t++) {
        scan_step(sm, t ? d_ysA + (t - 1) * B * H : nullptr, d_g0, w_hh0, b_hh0,
                  d_ysA + t * B * H);
        grid_sync();
    }

    // g1 = ysA @ w_ih1^T + b_ih1
    gate_gemm(sm, d_ysA, w_ih1, b_ih1, d_gbuf, T * B);
    grid_sync();

    // layer 1 scan -> ysB
    for (int t = 0; t < T; t++) {
        scan_step(sm, t ? d_ysB + (t - 1) * B * H : nullptr, d_gbuf + t * B * H3,
                  w_hh1, b_hh1, d_ysB + t * B * H);
        grid_sync();
    }

    // g2 = ysB @ w_ih2^T + b_ih2 (reuse gbuf)
    gate_gemm(sm, d_ysB, w_ih2, b_ih2, d_gbuf, T * B);
    grid_sync();

    // layer 2 scan -> ysA (reused)
    for (int t = 0; t < T; t++) {
        scan_step(sm, t ? d_ysA + (t - 1) * B * H : nullptr, d_gbuf + t * B * H3,
                  w_hh2, b_hh2, d_ysA + t * B * H);
        grid_sync();
    }

    // fc2 + permute
    fc2_phase(sm, d_ysA, fc2_w, fc2_b, out);
}

extern "C" void kernel_launch(void* const* d_in, const int* in_sizes, int n_in,
                              void* d_out, int out_size) {
    const float* x     = (const float*)d_in[0];
    const float* fc1_w = (const float*)d_in[1];
    const float* fc1_b = (const float*)d_in[2];
    const float* w_ih0 = (const float*)d_in[3];
    const float* w_hh0 = (const float*)d_in[4];
    const float* b_ih0 = (const float*)d_in[5];
    const float* b_hh0 = (const float*)d_in[6];
    const float* w_ih1 = (const float*)d_in[7];
    const float* w_hh1 = (const float*)d_in[8];
    const float* b_ih1 = (const float*)d_in[9];
    const float* b_hh1 = (const float*)d_in[10];
    const float* w_ih2 = (const float*)d_in[11];
    const float* w_hh2 = (const float*)d_in[12];
    const float* b_ih2 = (const float*)d_in[13];
    const float* b_hh2 = (const float*)d_in[14];
    const float* fc2_w = (const float*)d_in[15];
    const float* fc2_b = (const float*)d_in[16];
    float* out = (float*)d_out;

    decoder_kernel<<<NBLK, NTHR>>>(x, fc1_w, fc1_b,
                                   w_ih0, w_hh0, b_ih0, b_hh0,
                                   w_ih1, w_hh1, b_ih1, b_hh1,
                                   w_ih2, w_hh2, b_ih2, b_hh2,
                                   fc2_w, fc2_b, out);
}

// round 2
// speedup vs baseline: 1.0007x; 1.0007x over previous
#include <cuda_runtime.h>
#include <math.h>

#define D 56
#define H 501
#define T 277
#define O 76
#define B 256
#define H3 1503
#define NBLK 128
#define NTHR 256
#define KC 32
#define BM 64
#define BN 16   /* per gate */

// ---------------- static device scratch (no allocations allowed) ----------------
__device__ float d_hin[B * D];
__device__ float d_g0[B * H3];
__device__ float d_ysA[T * B * H];     // 142 MB
__device__ float d_ysB[T * B * H];     // 142 MB
__device__ float d_gbuf[T * B * H3];   // 426 MB (reused for g1 then g2)

// ---------------- grid barrier ----------------
__device__ unsigned int g_arrive = 0;
__device__ volatile unsigned int g_gen = 0;

__device__ __forceinline__ void grid_sync() {
    __syncthreads();
    if (threadIdx.x == 0) {
        __threadfence();
        unsigned int gen = g_gen;
        if (atomicAdd(&g_arrive, 1u) == (unsigned)(NBLK - 1)) {
            g_arrive = 0;
            __threadfence();
            g_gen = gen + 1;
        } else {
            while (g_gen == gen) { }
        }
        __threadfence();
    }
    __syncthreads();
}

// ---------------- packed f32x2 helpers ----------------
__device__ __forceinline__ unsigned long long dup_f32(float x) {
    unsigned long long r;
    unsigned int u = __float_as_uint(x);
    asm("mov.b64 %0, {%1, %1};" : "=l"(r) : "r"(u));
    return r;
}
__device__ __forceinline__ unsigned long long ffma2(unsigned long long a,
                                                    unsigned long long b,
                                                    unsigned long long c) {
    unsigned long long d;
    asm("fma.rn.f32x2 %0, %1, %2, %3;" : "=l"(d) : "l"(a), "l"(b), "l"(c));
    return d;
}
__device__ __forceinline__ float2 unpack2(unsigned long long v) {
    unsigned int lo, hi;
    asm("mov.b64 {%0, %1}, %2;" : "=r"(lo), "=r"(hi) : "l"(v));
    return make_float2(__uint_as_float(lo), __uint_as_float(hi));
}

// ---------------- shared memory ----------------
struct SMemG {
    float hs[KC][BM + 2];        // k-major h tile (pad 2 keeps 8B align + fewer conflicts)
    float ws[3][KC][BN + 1];     // 3-gate W tile
};
union SMem {
    SMemG g;
    float rows[8][H + 1];        // fc2 staging
};

// ---------------- fused 3-gate tile GEMM: acc[g] = hsrc(m0:m0+64,:) . W[g*H+n0+j,:] ----------------
__device__ __forceinline__ void tile3(SMem& sm, const float* __restrict__ hsrc,
                                      const float* __restrict__ W,
                                      int m0, int n0, unsigned long long acc[3][2]) {
    const int tid = threadIdx.x;
    const int tx = tid & 15;
    const int mrow = (tid >> 4) * 4;
    acc[0][0] = acc[0][1] = acc[1][0] = acc[1][1] = acc[2][0] = acc[2][1] = 0ull;
    if (hsrc == nullptr) return;  // h == 0 -> hg == 0 (uniform across block)

    const int lm = tid >> 5;   // 0..7
    const int lk = tid & 31;

    for (int k0 = 0; k0 < H; k0 += KC) {
        // stage h tile (k-major)
#pragma unroll
        for (int i = 0; i < 8; i++) {
            int mm = lm + i * 8;
            int k = k0 + lk;
            float v = (k < H) ? hsrc[(m0 + mm) * H + k] : 0.f;
            sm.g.hs[lk][mm] = v;
        }
        // stage 3-gate W tile
#pragma unroll
        for (int i = 0; i < 6; i++) {
            int e = tid + i * NTHR;
            int g = e >> 9;
            int rem = e & 511;
            int j = rem >> 5;
            int kk = rem & 31;
            int n = n0 + j;
            int k = k0 + kk;
            float v = (n < H && k < H) ? W[(g * H + n) * H + k] : 0.f;
            sm.g.ws[g][kk][j] = v;
        }
        __syncthreads();
#pragma unroll
        for (int kk = 0; kk < KC; kk++) {
            unsigned long long hp0 = *(const unsigned long long*)&sm.g.hs[kk][mrow];
            unsigned long long hp1 = *(const unsigned long long*)&sm.g.hs[kk][mrow + 2];
            unsigned long long w0 = dup_f32(sm.g.ws[0][kk][tx]);
            unsigned long long w1 = dup_f32(sm.g.ws[1][kk][tx]);
            unsigned long long w2 = dup_f32(sm.g.ws[2][kk][tx]);
            acc[0][0] = ffma2(hp0, w0, acc[0][0]);
            acc[0][1] = ffma2(hp1, w0, acc[0][1]);
            acc[1][0] = ffma2(hp0, w1, acc[1][0]);
            acc[1][1] = ffma2(hp1, w1, acc[1][1]);
            acc[2][0] = ffma2(hp0, w2, acc[2][0]);
            acc[2][1] = ffma2(hp1, w2, acc[2][1]);
        }
        __syncthreads();
    }
}

// ---------------- one GRU timestep (all 128 blocks, one tile each) ----------------
__device__ void scan_step(SMem& sm, const float* __restrict__ hprev,
                          const float* __restrict__ g,
                          const float* __restrict__ Whh,
                          const float* __restrict__ bhh,
                          float* __restrict__ hout) {
    const int tile = blockIdx.x;   // 0..127 = 4 M-tiles x 32 N-tiles
    const int mt = tile >> 5;
    const int nt = tile & 31;
    const int m0 = mt * BM;
    const int n0 = nt * BN;

    unsigned long long acc[3][2];
    tile3(sm, hprev, Whh, m0, n0, acc);

    const int tx = threadIdx.x & 15;
    const int ty = threadIdx.x >> 4;
    const int n = n0 + tx;
    if (n < H) {
        const float br = bhh[n];
        const float bz = bhh[H + n];
        const float bn = bhh[2 * H + n];
        float2 r0 = unpack2(acc[0][0]), r1 = unpack2(acc[0][1]);
        float2 z0 = unpack2(acc[1][0]), z1 = unpack2(acc[1][1]);
        float2 n0v = unpack2(acc[2][0]), n1v = unpack2(acc[2][1]);
        float ar[4] = {r0.x, r0.y, r1.x, r1.y};
        float az[4] = {z0.x, z0.y, z1.x, z1.y};
        float an[4] = {n0v.x, n0v.y, n1v.x, n1v.y};
#pragma unroll
        for (int i = 0; i < 4; i++) {
            const int m = m0 + ty * 4 + i;
            const float hp = hprev ? hprev[m * H + n] : 0.f;
            const float* gr = g + m * H3;
            float r = 1.f / (1.f + __expf(-(gr[n] + ar[i] + br)));
            float z = 1.f / (1.f + __expf(-(gr[H + n] + az[i] + bz)));
            float nn = tanhf(gr[2 * H + n] + r * (an[i] + bn));
            hout[m * H + n] = (1.f - z) * nn + z * hp;
        }
    }
}

// ---------------- batched input-gate GEMM: G(M x 3H) = Y(M x H) . Wih^T + bih ----------------
__device__ void gate_gemm(SMem& sm, const float* __restrict__ Y,
                          const float* __restrict__ Wih,
                          const float* __restrict__ bih,
                          float* __restrict__ G, int M) {
    const int Mtiles = M / BM;
    const int total = Mtiles * 32;
    for (int tile = blockIdx.x; tile < total; tile += NBLK) {
        const int mt = tile >> 5;
        const int nt = tile & 31;
        const int m0 = mt * BM;
        const int n0 = nt * BN;

        unsigned long long acc[3][2];
        tile3(sm, Y, Wih, m0, n0, acc);

        const int tx = threadIdx.x & 15;
        const int ty = threadIdx.x >> 4;
        const int n = n0 + tx;
        if (n < H) {
#pragma unroll
            for (int g = 0; g < 3; g++) {
                float2 p0 = unpack2(acc[g][0]);
                float2 p1 = unpack2(acc[g][1]);
                float a[4] = {p0.x, p0.y, p1.x, p1.y};
                const float bb = bih[g * H + n];
#pragma unroll
                for (int i = 0; i < 4; i++) {
                    const int m = m0 + ty * 4 + i;
                    G[m * H3 + g * H + n] = a[i] + bb;
                }
            }
        }
    }
}

// ---------------- fc2 + permute to (B, O, T) ----------------
__device__ void fc2_phase(SMem& sm, const float* __restrict__ Y,
                          const float* __restrict__ W,
                          const float* __restrict__ bias,
                          float* __restrict__ out) {
    const int wid = threadIdx.x >> 5;
    const int lane = threadIdx.x & 31;
    const int M = T * B;
    for (int base = blockIdx.x * 8; base < M; base += NBLK * 8) {
        const int row = base + wid;
        if (row < M) {
            for (int k = lane; k < H; k += 32) sm.rows[wid][k] = Y[row * H + k];
            __syncwarp();
            const int t = row / B;
            const int b = row % B;
            for (int o = lane; o < O; o += 32) {
                float acc = bias[o];
                const float* w = W + o * H;
                for (int k = 0; k < H; k++) acc += sm.rows[wid][k] * w[k];
                out[(b * O + o) * T + t] = acc;
            }
            __syncwarp();
        }
    }
}

// ---------------- persistent mega-kernel ----------------
__global__ void __launch_bounds__(NTHR) decoder_kernel(
    const float* __restrict__ x,
    const float* __restrict__ fc1_w, const float* __restrict__ fc1_b,
    const float* __restrict__ w_ih0, const float* __restrict__ w_hh0,
    const float* __restrict__ b_ih0, const float* __restrict__ b_hh0,
    const float* __restrict__ w_ih1, const float* __restrict__ w_hh1,
    const float* __restrict__ b_ih1, const float* __restrict__ b_hh1,
    const float* __restrict__ w_ih2, const float* __restrict__ w_hh2,
    const float* __restrict__ b_ih2, const float* __restrict__ b_hh2,
    const float* __restrict__ fc2_w, const float* __restrict__ fc2_b,
    float* __restrict__ out) {
    __shared__ SMem sm;
    const int gt = blockIdx.x * NTHR + threadIdx.x;
    const int GT = NBLK * NTHR;

    // fc1 + relu
    for (int i = gt; i < B * D; i += GT) {
        const int b = i / D, d = i % D;
        float acc = fc1_b[d];
        for (int k = 0; k < D; k++) acc += x[b * D + k] * fc1_w[d * D + k];
        d_hin[i] = fmaxf(acc, 0.f);
    }
    grid_sync();

    // g0 = h_in @ w_ih0^T + b_ih0 (constant over t)
    for (int i = gt; i < B * H3; i += GT) {
        const int b = i / H3, j = i % H3;
        float acc = b_ih0[j];
        for (int k = 0; k < D; k++) acc += d_hin[b * D + k] * w_ih0[j * D + k];
        d_g0[i] = acc;
    }
    grid_sync();

    // layer 0 scan -> ysA
    for (int t = 0; t < T; t++) {
        scan_step(sm, t ? d_ysA + (t - 1) * B * H : nullptr, d_g0, w_hh0, b_hh0,
                  d_ysA + t * B * H);
        grid_sync();
    }

    // g1 = ysA @ w_ih1^T + b_ih1
    gate_gemm(sm, d_ysA, w_ih1, b_ih1, d_gbuf, T * B);
    grid_sync();

    // layer 1 scan -> ysB
    for (int t = 0; t < T; t++) {
        scan_step(sm, t ? d_ysB + (t - 1) * B * H : nullptr, d_gbuf + t * B * H3,
                  w_hh1, b_hh1, d_ysB + t * B * H);
        grid_sync();
    }

    // g2 = ysB @ w_ih2^T + b_ih2 (reuse gbuf)
    gate_gemm(sm, d_ysB, w_ih2, b_ih2, d_gbuf, T * B);
    grid_sync();

    // layer 2 scan -> ysA (reused)
    for (int t = 0; t < T; t++) {
        scan_step(sm, t ? d_ysA + (t - 1) * B * H : nullptr, d_gbuf + t * B * H3,
                  w_hh2, b_hh2, d_ysA + t * B * H);
        grid_sync();
    }

    // fc2 + permute
    fc2_phase(sm, d_ysA, fc2_w, fc2_b, out);
}

extern "C" void kernel_launch(void* const* d_in, const int* in_sizes, int n_in,
                              void* d_out, int out_size) {
    const float* x     = (const float*)d_in[0];
    const float* fc1_w = (const float*)d_in[1];
    const float* fc1_b = (const float*)d_in[2];
    const float* w_ih0 = (const float*)d_in[3];
    const float* w_hh0 = (const float*)d_in[4];
    const float* b_ih0 = (const float*)d_in[5];
    const float* b_hh0 = (const float*)d_in[6];
    const float* w_ih1 = (const float*)d_in[7];
    const float* w_hh1 = (const float*)d_in[8];
    const float* b_ih1 = (const float*)d_in[9];
    const float* b_hh1 = (const float*)d_in[10];
    const float* w_ih2 = (const float*)d_in[11];
    const float* w_hh2 = (const float*)d_in[12];
    const float* b_ih2 = (const float*)d_in[13];
    const float* b_hh2 = (const float*)d_in[14];
    const float* fc2_w = (const float*)d_in[15];
    const float* fc2_b = (const float*)d_in[16];
    float* out = (float*)d_out;

    decoder_kernel<<<NBLK, NTHR>>>(x, fc1_w, fc1_b,
                                   w_ih0, w_hh0, b_ih0, b_hh0,
                                   w_ih1, w_hh1, b_ih1, b_hh1,
                                   w_ih2, w_hh2, b_ih2, b_hh2,
                                   fc2_w, fc2_b, out);
}